// round 7
// baseline (speedup 1.0000x reference)
#include <cuda_runtime.h>
#include <cstdint>

// Problem constants (fixed by the reference setup)
#define BB 32
#define SS 32
#define AA 512
#define VOCAB 32000
#define SENTINEL 0x7FFFFFFF
#define NBKT 128            // bucket = m >> 8 (0..124), sentinel bucket 127

// ---------------------------------------------------------------------------
// Kernel 1: pure streaming copy. 8 independent float4 per thread (MLP=8),
// fully coalesced, branchless, evict-first on both sides (262 MB stream
// should not thrash L2, which must keep seq/tbl/att hot for kernel 2).
// 2000 blocks x 512 threads x 8 float4 = 8,192,000 float4s.
// ---------------------------------------------------------------------------
__global__ void __launch_bounds__(512)
pg_copy_kernel(const float4* __restrict__ src, float4* __restrict__ dst) {
    size_t base = (size_t)blockIdx.x * 4096 + threadIdx.x;
    float4 r0 = __ldcs(src + base);
    float4 r1 = __ldcs(src + base + 512);
    float4 r2 = __ldcs(src + base + 1024);
    float4 r3 = __ldcs(src + base + 1536);
    float4 r4 = __ldcs(src + base + 2048);
    float4 r5 = __ldcs(src + base + 2560);
    float4 r6 = __ldcs(src + base + 3072);
    float4 r7 = __ldcs(src + base + 3584);
    __stcs(dst + base,        r0);
    __stcs(dst + base + 512,  r1);
    __stcs(dst + base + 1024, r2);
    __stcs(dst + base + 1536, r3);
    __stcs(dst + base + 2048, r4);
    __stcs(dst + base + 2560, r5);
    __stcs(dst + base + 3072, r6);
    __stcs(dst + base + 3584, r7);
}

// ---------------------------------------------------------------------------
// Kernel 2: fused gather + in-block counting sort + scatter-max.
// One block per (b,s) row (1024 blocks). Each block:
//   1. gathers m = tbl[seq[b, i]] for its batch (redundant across the 32
//      blocks sharing b, but seq/tbl are L2-hot and 1024 blocks hide the
//      gather latency that starved the standalone 32-block sort kernel),
//   2. counting-sorts the 512 (m,a) pairs into 128 buckets of m>>8 in smem
//      (1KB output granularity -> DRAM-row-friendly atomic ordering),
//   3. fires one atomicMax per pair; a warp's 32 atomics land in a narrow
//      ascending vocab window. Result unused -> RED, no return trip.
// Non-negative floats: signed-int max == float max (rel_err=0 confirmed).
// m==1 pairs become SENTINEL (skipped); zeroing out[:,:,1] here is thus
// equivalent to the reference's post-max zeroing.
// ---------------------------------------------------------------------------
__global__ void __launch_bounds__(512)
pg_scatter_kernel(const float* __restrict__ att,
                  const int*   __restrict__ seq,
                  const int*   __restrict__ tbl,
                  float*       __restrict__ out) {
    __shared__ int hist[NBKT];
    __shared__ int offs[NBKT];
    __shared__ int sorted[AA];

    unsigned bs = blockIdx.x;          // b*S + s  (0 .. 1023)
    unsigned b  = bs >> 5;
    int i = threadIdx.x;

    if (i < NBKT) hist[i] = 0;
    __syncthreads();

    int m = tbl[seq[(b << 9) + i]];
    int bkt    = (m == 1) ? (NBKT - 1) : (m >> 8);
    int packed = (m == 1) ? SENTINEL   : ((m << 9) | i);
    int rank   = atomicAdd(&hist[bkt], 1);
    __syncthreads();

    // Exclusive scan of 128 bucket counts by warp 0 (4 elems/lane + shfl).
    if (i < 32) {
        int c0 = hist[i * 4 + 0], c1 = hist[i * 4 + 1];
        int c2 = hist[i * 4 + 2], c3 = hist[i * 4 + 3];
        int lsum = c0 + c1 + c2 + c3;
        int pre  = lsum;
        #pragma unroll
        for (int d = 1; d < 32; d <<= 1) {
            int n = __shfl_up_sync(0xFFFFFFFF, pre, d);
            if (i >= d) pre += n;
        }
        pre -= lsum;
        offs[i * 4 + 0] = pre;
        offs[i * 4 + 1] = pre + c0;
        offs[i * 4 + 2] = pre + c0 + c1;
        offs[i * 4 + 3] = pre + c0 + c1 + c2;
    }
    __syncthreads();

    sorted[offs[bkt] + rank] = packed;
    __syncthreads();

    if (i == 0) out[(size_t)bs * VOCAB + 1] = 0.0f;   // out[:, :, 1] = 0

    int p = sorted[i];
    if (p != SENTINEL) {
        int mm = p >> 9;
        int a  = p & (AA - 1);
        float v = att[(size_t)bs * AA + a];
        atomicMax((int*)out + (size_t)bs * VOCAB + mm, __float_as_int(v));
    }
}

// ---------------------------------------------------------------------------
// Launch
// Inputs (metadata order):
//   d_in[0] decoder_outputs  f32 [B,S,VOCAB]
//   d_in[1] attention_scores f32 [B,S,A]
//   d_in[2] input_sequence   i32 [B,A]
//   d_in[3] repeat_idx       i32 [S,1]   (unused)
//   d_in[4] repeat_idx2      i32 [B,1]   (unused)
//   d_in[5] convert_table    i32 [SRC_VOCAB]
// Output: f32 [B,S,VOCAB]
// ---------------------------------------------------------------------------
extern "C" void kernel_launch(void* const* d_in, const int* in_sizes, int n_in,
                              void* d_out, int out_size) {
    const float4* dec = (const float4*)d_in[0];
    const float*  att = (const float*)d_in[1];
    const int*    seq = (const int*)d_in[2];
    const int*    tbl = (const int*)d_in[5];
    float*        out = (float*)d_out;

    const int n4 = BB * SS * VOCAB / 4;                 // 8,192,000
    pg_copy_kernel<<<n4 / 4096, 512>>>(dec, (float4*)out);

    pg_scatter_kernel<<<BB * SS, AA>>>(att, seq, tbl, out);
}